// round 13
// baseline (speedup 1.0000x reference)
#include <cuda_runtime.h>
#include <cuda_fp16.h>
#include <math.h>
#include <cstdint>

#define BATCH 2
#define NTOK  2304
#define CDIM  768
#define NH    12
#define HD    64
#define HWID  48
#define NELEM (BATCH*NH*NTOK*HD)

// ---------------- scratch (fp16 operands, fp32 final) ----------------
__device__ __half g_qinh [BATCH*NTOK*CDIM];
__device__ __half g_kvinh[BATCH*NTOK*CDIM];
__device__ __half g_qwh [CDIM*CDIM];
__device__ __half g_kvwh[2*CDIM*CDIM];
__device__ __half g_pwh [CDIM*CDIM];
__device__ __half g_Qh [NELEM];          // [bh][n][d]  (pre-scaled by 0.125*log2e)
__device__ __half g_Kh [NELEM];          // [bh][n][d]
__device__ __half g_Vh [NELEM];          // [bh][n][d]  (row-major; trans via ldmatrix)
__device__ __half g_Oh [NELEM];          // [bh][n][d]
__device__ float  g_P[BATCH*NTOK*CDIM];
__device__ float  g_psum [BATCH*NTOK];   // fused channel-sum (atomic)
__device__ int    g_pmaxi[BATCH*NTOK];   // fused channel-max (int-key atomic)

// ---------------- helpers ----------------
__device__ __forceinline__ uint32_t s2u(const void* p){
    uint32_t a;
    asm("{ .reg .u64 t; cvta.to.shared.u64 t, %1; cvt.u32.u64 %0, t; }" : "=r"(a) : "l"(p));
    return a;
}
__device__ __forceinline__ unsigned h2(float lo, float hi){
    __half2 v = __floats2half2_rn(lo, hi);
    return reinterpret_cast<unsigned&>(v);
}
__device__ __forceinline__ void mma16(float* d, const unsigned* a, const unsigned* b){
    asm volatile("mma.sync.aligned.m16n8k16.row.col.f32.f16.f16.f32 "
        "{%0,%1,%2,%3},{%4,%5,%6,%7},{%8,%9},{%0,%1,%2,%3};"
        : "+f"(d[0]),"+f"(d[1]),"+f"(d[2]),"+f"(d[3])
        : "r"(a[0]),"r"(a[1]),"r"(a[2]),"r"(a[3]),"r"(b[0]),"r"(b[1]));
}
__device__ __forceinline__ void cpa(uint32_t s, const void* g){
    asm volatile("cp.async.cg.shared.global [%0], [%1], 16;" :: "r"(s), "l"(g));
}
__device__ __forceinline__ void ldm4(unsigned* r, uint32_t a){
    asm volatile("ldmatrix.sync.aligned.m8n8.x4.shared.b16 {%0,%1,%2,%3}, [%4];"
        : "=r"(r[0]),"=r"(r[1]),"=r"(r[2]),"=r"(r[3]) : "r"(a));
}
__device__ __forceinline__ void ldm4t(unsigned* r, uint32_t a){
    asm volatile("ldmatrix.sync.aligned.m8n8.x4.trans.shared.b16 {%0,%1,%2,%3}, [%4];"
        : "=r"(r[0]),"=r"(r[1]),"=r"(r[2]),"=r"(r[3]) : "r"(a));
}
// order-preserving float->int key (involution)
__device__ __forceinline__ int fkey(float f){
    int i = __float_as_int(f);
    return (i >= 0) ? i : (i ^ 0x7FFFFFFF);
}
#define CP_COMMIT() asm volatile("cp.async.commit_group;" ::: "memory")
#define CP_WAIT0()  asm volatile("cp.async.wait_group 0;" ::: "memory")
#define CP_WAIT1()  asm volatile("cp.async.wait_group 1;" ::: "memory")

// ---------------- one-shot fp32 -> fp16 conversion + pool-acc init ----------------
__global__ __launch_bounds__(256) void cvt_all(const float* __restrict__ qi,
                                               const float* __restrict__ kvi,
                                               const float* __restrict__ qw,
                                               const float* __restrict__ kvw,
                                               const float* __restrict__ pw)
{
    int u = blockIdx.x*256 + threadIdx.x;       // float4 units
    if (u < BATCH*NTOK){ g_psum[u] = 0.f; g_pmaxi[u] = 0x80000000; }
    const int S0 = BATCH*NTOK*CDIM/4;
    const int S1 = S0*2;
    const int S2 = S1 + CDIM*CDIM/4;
    const int S3 = S2 + 2*CDIM*CDIM/4;
    const int S4 = S3 + CDIM*CDIM/4;
    if (u >= S4) return;
    const float* src; __half* dst; int off;
    if      (u < S0){ src = qi;  dst = g_qinh;  off = u; }
    else if (u < S1){ src = kvi; dst = g_kvinh; off = u - S0; }
    else if (u < S2){ src = qw;  dst = g_qwh;   off = u - S1; }
    else if (u < S3){ src = kvw; dst = g_kvwh;  off = u - S2; }
    else            { src = pw;  dst = g_pwh;   off = u - S3; }
    float4 v = ((const float4*)src)[off];
    ((uint2*)dst)[off] = make_uint2(h2(v.x, v.y), h2(v.z, v.w));
}

// ---------------- fp16 GEMM: 64M x 128N CTA, 128 thr, 3 CTAs/SM ----------------
// 4 warps (2m x 2n) of 32x64; k-chunk 64 halves, XOR-swizzled 128B rows.
// Stage = A 8KB + B 16KB = 24576 B; 3 stages, 2 tiles in flight.
// MODE 0: fused QKV (grid.x 18: 0-5 Q, 6-17 KV); MODE 2: proj -> g_P + fused pooling.
template<int MODE>
__global__ __launch_bounds__(128,3) void gemm_h2(const float* __restrict__ bias0,
                                                 const float* __restrict__ bias1)
{
    extern __shared__ __align__(16) char dsm[];
    const uint32_t sbase = s2u(dsm);
    const int t = threadIdx.x, lane = t & 31, warp = t >> 5;
    const int g = lane >> 2, tig = lane & 3;
    const int wm = warp >> 1, wn = warp & 1;
    const int m0 = blockIdx.y * 64;
    const int n0g = blockIdx.x * 128;

    const __half* Ah = nullptr; const __half* Wh;
    if (MODE == 0){
        if (n0g < CDIM){ Ah = g_qinh;  Wh = g_qwh  + n0g*CDIM; }
        else           { Ah = g_kvinh; Wh = g_kvwh + (n0g - CDIM)*CDIM; }
    } else {
        Wh = g_pwh + n0g*CDIM;
    }

    auto issue = [&](int kt, int stg){
        const uint32_t so = sbase + (uint32_t)stg*24576u;
        #pragma unroll
        for (int p = 0; p < 4; p++){
            int ch = t + p*128;
            int row = ch >> 3, c = ch & 7;
            uint32_t sw = (uint32_t)((c ^ (row & 7)) << 4);
            const __half* ga;
            if (MODE == 2){
                int m = m0 + row; int b = m >= NTOK, n = m - b*NTOK;
                ga = g_Oh + (((b*NH + kt)*NTOK + n) << 6) + c*8;
            } else {
                ga = Ah + (m0 + row)*CDIM + kt*64 + c*8;
            }
            cpa(so + row*128 + sw, ga);
        }
        #pragma unroll
        for (int p = 0; p < 8; p++){
            int ch = t + p*128;
            int row = ch >> 3, c = ch & 7;
            uint32_t sw = (uint32_t)((c ^ (row & 7)) << 4);
            cpa(so + 8192 + row*128 + sw, Wh + row*CDIM + kt*64 + c*8);
        }
        CP_COMMIT();
    };

    float acc[2][8][4] = {};
    issue(0, 0); issue(1, 1);

    const int arow = wm*32 + (lane & 15);
    const int ac0  = lane >> 4;
    const int brow = wn*64 + (lane & 7) + ((lane>>4)<<3);
    const int bc0  = (lane>>3) & 1;
    const int x7   = lane & 7;

    const int NK = CDIM/64;              // 12
    for (int kt = 0; kt < NK; kt++){
        CP_WAIT1();
        __syncthreads();
        if (kt + 2 < NK) issue(kt+2, (kt+2)%3);
        const uint32_t so = sbase + (uint32_t)(kt%3)*24576u;
        #pragma unroll
        for (int kk = 0; kk < 4; kk++){
            unsigned af[2][4], bf[4][4];
            #pragma unroll
            for (int i = 0; i < 2; i++)
                ldm4(af[i], so + (arow + i*16)*128 + (((2*kk + ac0) ^ x7) << 4));
            #pragma unroll
            for (int jp = 0; jp < 4; jp++)
                ldm4(bf[jp], so + 8192 + (brow + jp*16)*128 + (((2*kk + bc0) ^ x7) << 4));
            #pragma unroll
            for (int i = 0; i < 2; i++)
                #pragma unroll
                for (int j = 0; j < 8; j++)
                    mma16(acc[i][j], af[i], &bf[j>>1][(j&1)*2]);
        }
    }

    // epilogue
    if (MODE == 2){
        #pragma unroll
        for (int i = 0; i < 2; i++){
            #pragma unroll
            for (int hh = 0; hh < 2; hh++){
                int r = m0 + wm*32 + i*16 + g + hh*8;   // = b*NTOK + n
                float rs = 0.f, rm = -INFINITY;
                #pragma unroll
                for (int j = 0; j < 8; j++){
                    int c0g = n0g + wn*64 + j*8 + 2*tig;
                    float xv = acc[i][j][hh*2+0] + bias0[c0g];
                    float yv = acc[i][j][hh*2+1] + bias0[c0g+1];
                    *(float2*)&g_P[r*CDIM + c0g] = make_float2(xv, yv);
                    rs += xv + yv;
                    rm = fmaxf(rm, fmaxf(xv, yv));
                }
                rs += __shfl_xor_sync(0xffffffffu, rs, 1);
                rs += __shfl_xor_sync(0xffffffffu, rs, 2);
                rm = fmaxf(rm, __shfl_xor_sync(0xffffffffu, rm, 1));
                rm = fmaxf(rm, __shfl_xor_sync(0xffffffffu, rm, 2));
                if (tig == 0){
                    atomicAdd(&g_psum[r], rs);
                    atomicMax(&g_pmaxi[r], fkey(rm));
                }
            }
        }
    } else {
        const float SCQ = 0.18033688f;   // 0.125 * log2(e), folded into Q
        #pragma unroll
        for (int i = 0; i < 2; i++){
            #pragma unroll
            for (int j = 0; j < 8; j++){
                int r0 = m0 + wm*32 + i*16 + g;
                int c0g = n0g + wn*64 + j*8 + 2*tig;
                #pragma unroll
                for (int hh = 0; hh < 2; hh++){
                    int r = r0 + hh*8;
                    int b = r >= NTOK, n = r - b*NTOK;
                    float xv = acc[i][j][hh*2+0], yv = acc[i][j][hh*2+1];
                    if (c0g < CDIM){
                        xv = (xv + bias0[c0g]) * SCQ;
                        yv = (yv + bias0[c0g+1]) * SCQ;
                        *(__half2*)&g_Qh[(((b*NH + (c0g>>6))*NTOK + n) << 6) + (c0g & 63)] =
                            __floats2half2_rn(xv, yv);
                    } else {
                        int ck = c0g - CDIM;
                        xv += bias1[ck]; yv += bias1[ck+1];
                        __half* dst = (ck < CDIM) ? g_Kh : g_Vh;
                        int cc = (ck < CDIM) ? ck : (ck - CDIM);
                        *(__half2*)&dst[(((b*NH + (cc>>6))*NTOK + n) << 6) + (cc & 63)] =
                            __floats2half2_rn(xv, yv);
                    }
                }
            }
        }
    }
}

// ---------------- fp16 flash attention: 192 q/CTA, 384 thr, 12 warps ----------
// 12 warps x 16 q-rows; reg-P, f16x2 exp (scale pre-folded into Q),
// ones-mma row sums, V row-major + ldmatrix.trans for PV B-fragments.
// Grid 12 x 24 = 288 CTAs = 1.95 waves on 148 SMs.
// smem: Q [192 x 144B] | 3 x (K 64x144 + V 64x144) = 82944 B
__global__ __launch_bounds__(384,1) void attn_h3()
{
    extern __shared__ __align__(16) char dsm[];
    const uint32_t sbase = s2u(dsm);
    const int t = threadIdx.x, lane = t & 31, warp = t >> 5;
    const int g = lane >> 2, tig = lane & 3;
    const int bh = blockIdx.y, q0 = blockIdx.x * 192;

    const __half* Qg = g_Qh + (size_t)bh * NTOK * HD;
    const __half* Kg = g_Kh + (size_t)bh * NTOK * HD;
    const __half* Vg = g_Vh + (size_t)bh * NTOK * HD;
    __half*       Og = g_Oh + (size_t)bh * NTOK * HD;

    auto issueKV = [&](int kt, int buf, bool withQ){
        const int k0 = kt * 64;
        if (withQ){
            #pragma unroll
            for (int p = 0; p < 4; p++){
                int ch = t + p*384;
                int row = ch >> 3, c = ch & 7;
                cpa(sbase + row*144 + c*16, Qg + (q0 + row)*HD + c*8);
            }
        }
        const uint32_t kb = sbase + 27648 + (uint32_t)buf*18432u;
        #pragma unroll
        for (int p = 0; p < 3; p++){
            int ch = t + p*384;
            if (ch < 1024){
                int isv = ch >= 512;
                int cc = ch & 511;
                int row = cc >> 3, c = cc & 7;
                if (!isv) cpa(kb + row*144 + c*16, Kg + (k0 + row)*HD + c*8);
                else      cpa(kb + 9216 + row*144 + c*16, Vg + (k0 + row)*HD + c*8);
            }
        }
        CP_COMMIT();
    };

    issueKV(0, 0, true);     // [Q+KV0]
    issueKV(1, 1, false);    // [KV1]
    CP_WAIT1();
    __syncthreads();         // Q + KV0 ready

    const uint32_t qAddr = sbase + (warp*16 + (lane & 15))*144 + (lane>>4)*16;
    const uint32_t bOff  = ((lane & 7) + ((lane>>4)<<3))*144 + ((lane>>3)&1)*16;
    const uint32_t kvA   = sbase + 27648 + bOff;
    // trans-ldmatrix lane base for row-major V:
    //   row = ((lane>>3)&1)*8 + (lane&7), col halves = (lane>>4)*8
    const uint32_t vtOff = (uint32_t)((((lane>>3)&1)*8 + (lane&7))*144 + (lane>>4)*16);
    const uint32_t vAddrT = sbase + 27648 + 9216 + vtOff;

    // hoist Q fragments (tile-invariant): warp covers 16 q rows
    unsigned aq[4][4];
    #pragma unroll
    for (int kk = 0; kk < 4; kk++) ldm4(aq[kk], qAddr + kk*32);

    const unsigned ones = 0x3C003C00u;
    const unsigned onesv[2] = {ones, ones};

    float accO[8][4] = {};
    float accL[4] = {};                  // row sums via P @ 1 (fp32 tensor accum)

    const int NKT = NTOK/64;             // 36
    for (int kt = 0; kt < NKT; kt++){
        const uint32_t kb = (uint32_t)(kt%3)*18432u;
        if (kt){
            CP_WAIT1();
            __syncthreads();             // tile kt staged; PV(kt-1) fully retired
        }
        if (kt + 2 < NKT) issueKV(kt+2, (kt+2)%3, false);

        // ---- S = Q K^T  (Q pre-scaled by 0.125*log2e) ----
        float accS[8][4] = {};
        #pragma unroll
        for (int kk = 0; kk < 4; kk++){
            #pragma unroll
            for (int jp = 0; jp < 4; jp++){
                unsigned bk[4];
                ldm4(bk, kvA + kb + jp*2304 + kk*32);
                mma16(accS[2*jp  ], aq[kk], &bk[0]);
                mma16(accS[2*jp+1], aq[kk], &bk[2]);
            }
        }

        // ---- exp2 in f16x2, repack as PV A-fragments ----
        unsigned ap[4][4];
        #pragma unroll
        for (int jb = 0; jb < 8; jb++){
            __half2 p0 = __floats2half2_rn(accS[jb][0], accS[jb][1]);
            __half2 p1 = __floats2half2_rn(accS[jb][2], accS[jb][3]);
            __half2 e0 = h2exp2(p0);
            __half2 e1 = h2exp2(p1);
            ap[jb>>1][(jb&1)*2 + 0] = reinterpret_cast<unsigned&>(e0);
            ap[jb>>1][(jb&1)*2 + 1] = reinterpret_cast<unsigned&>(e1);
        }

        // ---- O += P @ V ; L += P @ 1  (V via ldmatrix.trans) ----
        #pragma unroll
        for (int c = 0; c < 4; c++){
            #pragma unroll
            for (int jp = 0; jp < 4; jp++){
                unsigned bv[4];
                ldm4t(bv, vAddrT + kb + c*2304 + jp*32);
                mma16(accO[2*jp  ], ap[c], &bv[0]);
                mma16(accO[2*jp+1], ap[c], &bv[2]);
            }
            mma16(accL, ap[c], onesv);
        }
    }

    // accL[0] = row sum (row g), accL[2] = row g+8
    const float inv0 = 1.0f / accL[0], inv1 = 1.0f / accL[2];

    const int r0 = q0 + warp*16 + g, r1 = r0 + 8;
    #pragma unroll
    for (int jb = 0; jb < 8; jb++){
        int c = jb*8 + 2*tig;
        *(__half2*)&Og[r0*HD + c] = __floats2half2_rn(accO[jb][0]*inv0, accO[jb][1]*inv0);
        *(__half2*)&Og[r1*HD + c] = __floats2half2_rn(accO[jb][2]*inv1, accO[jb][3]*inv1);
    }
}

// ---------------- fused 7x7x2 conv + sigmoid + gate multiply ----------------
// One block per token: thread 0 computes the conv+sigmoid, 192 threads scale.
__global__ __launch_bounds__(192) void convgate_k(const float* __restrict__ sa_w,
                                                  float* __restrict__ out)
{
    const int tok = blockIdx.x;          // b*NTOK + n
    __shared__ float sg;
    if (threadIdx.x == 0){
        int b = tok >= NTOK; int n = tok - b*NTOK;
        int hh = n / HWID, ww = n % HWID;
        const float AVS = 1.0f / CDIM;
        float acc = 0.f;
        #pragma unroll
        for (int ki = 0; ki < 7; ki++){
            int y = hh + ki - 3;
            if ((unsigned)y >= (unsigned)HWID) continue;
            #pragma unroll
            for (int kj = 0; kj < 7; kj++){
                int x = ww + kj - 3;
                if ((unsigned)x >= (unsigned)HWID) continue;
                int base = b*NTOK + y*HWID + x;
                float avg = g_psum[base] * AVS;
                int k = g_pmaxi[base];
                float mx = __int_as_float((k >= 0) ? k : (k ^ 0x7FFFFFFF));
                acc += sa_w[ki*7 + kj] * avg + sa_w[49 + ki*7 + kj] * mx;
            }
        }
        sg = 1.0f / (1.0f + __expf(-acc));
    }
    __syncthreads();
    const float gg = sg;
    float4 v = ((const float4*)(g_P + (size_t)tok*CDIM))[threadIdx.x];
    v.x *= gg; v.y *= gg; v.z *= gg; v.w *= gg;
    ((float4*)out)[(size_t)tok*(CDIM/4) + threadIdx.x] = v;
}

// ---------------- launch ----------------
extern "C" void kernel_launch(void* const* d_in, const int* in_sizes, int n_in,
                              void* d_out, int out_size)
{
    (void)in_sizes; (void)n_in; (void)out_size;
    const float* q_in   = (const float*)d_in[0];
    const float* kv_in  = (const float*)d_in[1];
    const float* q_w    = (const float*)d_in[2];
    const float* q_b    = (const float*)d_in[3];
    const float* kv_w   = (const float*)d_in[4];
    const float* kv_b   = (const float*)d_in[5];
    const float* proj_w = (const float*)d_in[6];
    const float* proj_b = (const float*)d_in[7];
    const float* sa_w   = (const float*)d_in[8];

    const int gemm_smem = 3 * 24576;        // 73728
    const int attn_smem = 27648 + 3*18432;  // 82944
    cudaFuncSetAttribute(gemm_h2<0>, cudaFuncAttributeMaxDynamicSharedMemorySize, gemm_smem);
    cudaFuncSetAttribute(gemm_h2<2>, cudaFuncAttributeMaxDynamicSharedMemorySize, gemm_smem);
    cudaFuncSetAttribute(attn_h3,    cudaFuncAttributeMaxDynamicSharedMemorySize, attn_smem);

    cvt_all<<<9216, 256>>>(q_in, kv_in, q_w, kv_w, proj_w);

    gemm_h2<0><<<dim3(18, 72), 128, gemm_smem>>>(q_b, kv_b);     // fused Q + KV proj

    attn_h3<<<dim3(12, 24), 384, attn_smem>>>();

    gemm_h2<2><<<dim3( 6, 72), 128, gemm_smem>>>(proj_b, nullptr);

    convgate_k<<<BATCH*NTOK, 192>>>(sa_w, (float*)d_out);
}

// round 15
// speedup vs baseline: 1.0745x; 1.0745x over previous
#include <cuda_runtime.h>
#include <cuda_fp16.h>
#include <math.h>
#include <cstdint>

#define BATCH 2
#define NTOK  2304
#define CDIM  768
#define NH    12
#define HD    64
#define HWID  48
#define NELEM (BATCH*NH*NTOK*HD)

// ---------------- scratch (fp16 operands, fp32 final) ----------------
__device__ __half g_qinh [BATCH*NTOK*CDIM];
__device__ __half g_kvinh[BATCH*NTOK*CDIM];
__device__ __half g_qwh [CDIM*CDIM];
__device__ __half g_kvwh[2*CDIM*CDIM];
__device__ __half g_pwh [CDIM*CDIM];
__device__ __half g_Qh [NELEM];          // [bh][n][d]  (pre-scaled by 0.125*log2e)
__device__ __half g_Kh [NELEM];          // [bh][n][d]
__device__ __half g_Vh [NELEM];          // [bh][n][d]  (row-major; trans via ldmatrix)
__device__ __half g_Oh [NELEM];          // [bh][n][d]
__device__ float  g_P[BATCH*NTOK*CDIM];
__device__ float  g_psum [BATCH*NTOK];   // fused channel-sum (atomic)
__device__ int    g_pmaxi[BATCH*NTOK];   // fused channel-max (int-key atomic)

// ---------------- helpers ----------------
__device__ __forceinline__ uint32_t s2u(const void* p){
    uint32_t a;
    asm("{ .reg .u64 t; cvta.to.shared.u64 t, %1; cvt.u32.u64 %0, t; }" : "=r"(a) : "l"(p));
    return a;
}
__device__ __forceinline__ unsigned h2(float lo, float hi){
    __half2 v = __floats2half2_rn(lo, hi);
    return reinterpret_cast<unsigned&>(v);
}
__device__ __forceinline__ void mma16(float* d, const unsigned* a, const unsigned* b){
    asm volatile("mma.sync.aligned.m16n8k16.row.col.f32.f16.f16.f32 "
        "{%0,%1,%2,%3},{%4,%5,%6,%7},{%8,%9},{%0,%1,%2,%3};"
        : "+f"(d[0]),"+f"(d[1]),"+f"(d[2]),"+f"(d[3])
        : "r"(a[0]),"r"(a[1]),"r"(a[2]),"r"(a[3]),"r"(b[0]),"r"(b[1]));
}
__device__ __forceinline__ void cpa(uint32_t s, const void* g){
    asm volatile("cp.async.cg.shared.global [%0], [%1], 16;" :: "r"(s), "l"(g));
}
__device__ __forceinline__ void ldm4(unsigned* r, uint32_t a){
    asm volatile("ldmatrix.sync.aligned.m8n8.x4.shared.b16 {%0,%1,%2,%3}, [%4];"
        : "=r"(r[0]),"=r"(r[1]),"=r"(r[2]),"=r"(r[3]) : "r"(a));
}
__device__ __forceinline__ void ldm4t(unsigned* r, uint32_t a){
    asm volatile("ldmatrix.sync.aligned.m8n8.x4.trans.shared.b16 {%0,%1,%2,%3}, [%4];"
        : "=r"(r[0]),"=r"(r[1]),"=r"(r[2]),"=r"(r[3]) : "r"(a));
}
// order-preserving float->int key (involution)
__device__ __forceinline__ int fkey(float f){
    int i = __float_as_int(f);
    return (i >= 0) ? i : (i ^ 0x7FFFFFFF);
}
#define CP_COMMIT() asm volatile("cp.async.commit_group;" ::: "memory")
#define CP_WAIT1()  asm volatile("cp.async.wait_group 1;" ::: "memory")

#define MB_INIT(mb,c) asm volatile("mbarrier.init.shared.b64 [%0], %1;" :: "r"(mb), "r"(c) : "memory")
__device__ __forceinline__ void mb_arrive(uint32_t mb){
    asm volatile("{\n\t.reg .b64 st;\n\tmbarrier.arrive.shared.b64 st, [%0];\n\t}" :: "r"(mb) : "memory");
}
__device__ __forceinline__ void cpa_mb_arrive(uint32_t mb){
    // .noinc is load-bearing: default variant bumps the expected-arrival count
    // and the deferred arrive nets to zero -> phase never completes (r14 hang).
    asm volatile("cp.async.mbarrier.arrive.noinc.shared.b64 [%0];" :: "r"(mb) : "memory");
}
__device__ __forceinline__ void mb_wait(uint32_t mb, uint32_t parity){
    asm volatile("{\n\t.reg .pred P;\n\tWL_%=:\n\t"
        "mbarrier.try_wait.parity.shared.b64 P, [%0], %1;\n\t"
        "@!P bra WL_%=;\n\t}" :: "r"(mb), "r"(parity) : "memory");
}

// ---------------- one-shot fp32 -> fp16 conversion + pool-acc init ----------------
__global__ __launch_bounds__(256) void cvt_all(const float* __restrict__ qi,
                                               const float* __restrict__ kvi,
                                               const float* __restrict__ qw,
                                               const float* __restrict__ kvw,
                                               const float* __restrict__ pw)
{
    int u = blockIdx.x*256 + threadIdx.x;       // float4 units
    if (u < BATCH*NTOK){ g_psum[u] = 0.f; g_pmaxi[u] = 0x80000000; }
    const int S0 = BATCH*NTOK*CDIM/4;
    const int S1 = S0*2;
    const int S2 = S1 + CDIM*CDIM/4;
    const int S3 = S2 + 2*CDIM*CDIM/4;
    const int S4 = S3 + CDIM*CDIM/4;
    if (u >= S4) return;
    const float* src; __half* dst; int off;
    if      (u < S0){ src = qi;  dst = g_qinh;  off = u; }
    else if (u < S1){ src = kvi; dst = g_kvinh; off = u - S0; }
    else if (u < S2){ src = qw;  dst = g_qwh;   off = u - S1; }
    else if (u < S3){ src = kvw; dst = g_kvwh;  off = u - S2; }
    else            { src = pw;  dst = g_pwh;   off = u - S3; }
    float4 v = ((const float4*)src)[off];
    ((uint2*)dst)[off] = make_uint2(h2(v.x, v.y), h2(v.z, v.w));
}

// ---------------- fp16 GEMM: 64M x 128N CTA, 128 thr, 3 CTAs/SM ----------------
// (unchanged from round 12/13 — best measured config)
template<int MODE>
__global__ __launch_bounds__(128,3) void gemm_h2(const float* __restrict__ bias0,
                                                 const float* __restrict__ bias1)
{
    extern __shared__ __align__(16) char dsm[];
    const uint32_t sbase = s2u(dsm);
    const int t = threadIdx.x, lane = t & 31, warp = t >> 5;
    const int g = lane >> 2, tig = lane & 3;
    const int wm = warp >> 1, wn = warp & 1;
    const int m0 = blockIdx.y * 64;
    const int n0g = blockIdx.x * 128;

    const __half* Ah = nullptr; const __half* Wh;
    if (MODE == 0){
        if (n0g < CDIM){ Ah = g_qinh;  Wh = g_qwh  + n0g*CDIM; }
        else           { Ah = g_kvinh; Wh = g_kvwh + (n0g - CDIM)*CDIM; }
    } else {
        Wh = g_pwh + n0g*CDIM;
    }

    auto issue = [&](int kt, int stg){
        const uint32_t so = sbase + (uint32_t)stg*24576u;
        #pragma unroll
        for (int p = 0; p < 4; p++){
            int ch = t + p*128;
            int row = ch >> 3, c = ch & 7;
            uint32_t sw = (uint32_t)((c ^ (row & 7)) << 4);
            const __half* ga;
            if (MODE == 2){
                int m = m0 + row; int b = m >= NTOK, n = m - b*NTOK;
                ga = g_Oh + (((b*NH + kt)*NTOK + n) << 6) + c*8;
            } else {
                ga = Ah + (m0 + row)*CDIM + kt*64 + c*8;
            }
            cpa(so + row*128 + sw, ga);
        }
        #pragma unroll
        for (int p = 0; p < 8; p++){
            int ch = t + p*128;
            int row = ch >> 3, c = ch & 7;
            uint32_t sw = (uint32_t)((c ^ (row & 7)) << 4);
            cpa(so + 8192 + row*128 + sw, Wh + row*CDIM + kt*64 + c*8);
        }
        CP_COMMIT();
    };

    float acc[2][8][4] = {};
    issue(0, 0); issue(1, 1);

    const int arow = wm*32 + (lane & 15);
    const int ac0  = lane >> 4;
    const int brow = wn*64 + (lane & 7) + ((lane>>4)<<3);
    const int bc0  = (lane>>3) & 1;
    const int x7   = lane & 7;

    const int NK = CDIM/64;              // 12
    for (int kt = 0; kt < NK; kt++){
        CP_WAIT1();
        __syncthreads();
        if (kt + 2 < NK) issue(kt+2, (kt+2)%3);
        const uint32_t so = sbase + (uint32_t)(kt%3)*24576u;
        #pragma unroll
        for (int kk = 0; kk < 4; kk++){
            unsigned af[2][4], bf[4][4];
            #pragma unroll
            for (int i = 0; i < 2; i++)
                ldm4(af[i], so + (arow + i*16)*128 + (((2*kk + ac0) ^ x7) << 4));
            #pragma unroll
            for (int jp = 0; jp < 4; jp++)
                ldm4(bf[jp], so + 8192 + (brow + jp*16)*128 + (((2*kk + bc0) ^ x7) << 4));
            #pragma unroll
            for (int i = 0; i < 2; i++)
                #pragma unroll
                for (int j = 0; j < 8; j++)
                    mma16(acc[i][j], af[i], &bf[j>>1][(j&1)*2]);
        }
    }

    // epilogue
    if (MODE == 2){
        #pragma unroll
        for (int i = 0; i < 2; i++){
            #pragma unroll
            for (int hh = 0; hh < 2; hh++){
                int r = m0 + wm*32 + i*16 + g + hh*8;   // = b*NTOK + n
                float rs = 0.f, rm = -INFINITY;
                #pragma unroll
                for (int j = 0; j < 8; j++){
                    int c0g = n0g + wn*64 + j*8 + 2*tig;
                    float xv = acc[i][j][hh*2+0] + bias0[c0g];
                    float yv = acc[i][j][hh*2+1] + bias0[c0g+1];
                    *(float2*)&g_P[r*CDIM + c0g] = make_float2(xv, yv);
                    rs += xv + yv;
                    rm = fmaxf(rm, fmaxf(xv, yv));
                }
                rs += __shfl_xor_sync(0xffffffffu, rs, 1);
                rs += __shfl_xor_sync(0xffffffffu, rs, 2);
                rm = fmaxf(rm, __shfl_xor_sync(0xffffffffu, rm, 1));
                rm = fmaxf(rm, __shfl_xor_sync(0xffffffffu, rm, 2));
                if (tig == 0){
                    atomicAdd(&g_psum[r], rs);
                    atomicMax(&g_pmaxi[r], fkey(rm));
                }
            }
        }
    } else {
        const float SCQ = 0.18033688f;   // 0.125 * log2(e), folded into Q
        #pragma unroll
        for (int i = 0; i < 2; i++){
            #pragma unroll
            for (int j = 0; j < 8; j++){
                int r0 = m0 + wm*32 + i*16 + g;
                int c0g = n0g + wn*64 + j*8 + 2*tig;
                #pragma unroll
                for (int hh = 0; hh < 2; hh++){
                    int r = r0 + hh*8;
                    int b = r >= NTOK, n = r - b*NTOK;
                    float xv = acc[i][j][hh*2+0], yv = acc[i][j][hh*2+1];
                    if (c0g < CDIM){
                        xv = (xv + bias0[c0g]) * SCQ;
                        yv = (yv + bias0[c0g+1]) * SCQ;
                        *(__half2*)&g_Qh[(((b*NH + (c0g>>6))*NTOK + n) << 6) + (c0g & 63)] =
                            __floats2half2_rn(xv, yv);
                    } else {
                        int ck = c0g - CDIM;
                        xv += bias1[ck]; yv += bias1[ck+1];
                        __half* dst = (ck < CDIM) ? g_Kh : g_Vh;
                        int cc = (ck < CDIM) ? ck : (ck - CDIM);
                        *(__half2*)&dst[(((b*NH + (cc>>6))*NTOK + n) << 6) + (cc & 63)] =
                            __floats2half2_rn(xv, yv);
                    }
                }
            }
        }
    }
}

// ---------------- fp16 flash attention: mbarrier pipeline, no mainloop syncthreads ----
// 192 q/CTA, 384 thr, 12 warps x 16 q-rows; reg-P, f16x2 exp, ones-mma row sums.
// 6 KV buffers with full/empty mbarrier pairs; cp.async tracked via
// cp.async.mbarrier.arrive.noinc. Warps drift up to 3 tiles -> exp/ldm overlap
// with other warps' HMMAs.
// smem: Q [192 x 144B] | 6 x (K 64x144 + V 64x144) = 138240 B
#define NBUF 6
__global__ __launch_bounds__(384,1) void attn_h3()
{
    extern __shared__ __align__(16) char dsm[];
    __shared__ __align__(8) uint64_t s_mbar[2*NBUF];   // full[6], empty[6]
    const uint32_t sbase = s2u(dsm);
    const uint32_t mbF = s2u(&s_mbar[0]);
    const uint32_t mbE = s2u(&s_mbar[NBUF]);
    const int t = threadIdx.x, lane = t & 31, warp = t >> 5;
    const int g = lane >> 2, tig = lane & 3;
    const int bh = blockIdx.y, q0 = blockIdx.x * 192;

    const __half* Qg = g_Qh + (size_t)bh * NTOK * HD;
    const __half* Kg = g_Kh + (size_t)bh * NTOK * HD;
    const __half* Vg = g_Vh + (size_t)bh * NTOK * HD;
    __half*       Og = g_Oh + (size_t)bh * NTOK * HD;

    if (t == 0){
        #pragma unroll
        for (int b = 0; b < NBUF; b++){
            MB_INIT(mbF + b*8, 384);
            MB_INIT(mbE + b*8, 384);
        }
    }
    __syncthreads();
    // init-arrive all empties: completes empty phase 0 (buffers free)
    #pragma unroll
    for (int b = 0; b < NBUF; b++) mb_arrive(mbE + b*8);

    auto issueKV = [&](int kt, bool withQ){
        const int buf = kt % NBUF;
        const uint32_t par = (uint32_t)((kt / NBUF) & 1);
        mb_wait(mbE + buf*8, par);                    // readers of tile kt-6 done
        const int k0 = kt * 64;
        if (withQ){
            #pragma unroll
            for (int p = 0; p < 4; p++){
                int ch = t + p*384;
                int row = ch >> 3, c = ch & 7;
                cpa(sbase + row*144 + c*16, Qg + (q0 + row)*HD + c*8);
            }
        }
        const uint32_t kb = sbase + 27648 + (uint32_t)buf*18432u;
        #pragma unroll
        for (int p = 0; p < 3; p++){
            int ch = t + p*384;
            if (ch < 1024){
                int isv = ch >= 512;
                int cc = ch & 511;
                int row = cc >> 3, c = cc & 7;
                if (!isv) cpa(kb + row*144 + c*16, Kg + (k0 + row)*HD + c*8);
                else      cpa(kb + 9216 + row*144 + c*16, Vg + (k0 + row)*HD + c*8);
            }
        }
        cpa_mb_arrive(mbF + buf*8);                   // arrive when this thread's copies land
    };

    issueKV(0, true); issueKV(1, false); issueKV(2, false);

    const uint32_t qAddr = sbase + (warp*16 + (lane & 15))*144 + (lane>>4)*16;
    const uint32_t bOff  = ((lane & 7) + ((lane>>4)<<3))*144 + ((lane>>3)&1)*16;
    const uint32_t kvA   = sbase + 27648 + bOff;
    const uint32_t vtOff = (uint32_t)((((lane>>3)&1)*8 + (lane&7))*144 + (lane>>4)*16);
    const uint32_t vAddrT = sbase + 27648 + 9216 + vtOff;

    // hoist Q fragments (arrive with buffer-0's full barrier)
    mb_wait(mbF + 0, 0);
    unsigned aq[4][4];
    #pragma unroll
    for (int kk = 0; kk < 4; kk++) ldm4(aq[kk], qAddr + kk*32);

    const unsigned ones = 0x3C003C00u;
    const unsigned onesv[2] = {ones, ones};

    float accO[8][4] = {};
    float accL[4] = {};

    const int NKT = NTOK/64;             // 36
    for (int kt = 0; kt < NKT; kt++){
        const int buf = kt % NBUF;
        const uint32_t kb = (uint32_t)buf*18432u;
        mb_wait(mbF + buf*8, (uint32_t)((kt / NBUF) & 1));   // tile kt staged (acquire)
        if (kt + 3 < NKT) issueKV(kt+3, false);

        // ---- S = Q K^T  (Q pre-scaled by 0.125*log2e) ----
        float accS[8][4] = {};
        #pragma unroll
        for (int kk = 0; kk < 4; kk++){
            #pragma unroll
            for (int jp = 0; jp < 4; jp++){
                unsigned bk[4];
                ldm4(bk, kvA + kb + jp*2304 + kk*32);
                mma16(accS[2*jp  ], aq[kk], &bk[0]);
                mma16(accS[2*jp+1], aq[kk], &bk[2]);
            }
        }

        // ---- exp2 in f16x2, repack as PV A-fragments ----
        unsigned ap[4][4];
        #pragma unroll
        for (int jb = 0; jb < 8; jb++){
            __half2 p0 = __floats2half2_rn(accS[jb][0], accS[jb][1]);
            __half2 p1 = __floats2half2_rn(accS[jb][2], accS[jb][3]);
            __half2 e0 = h2exp2(p0);
            __half2 e1 = h2exp2(p1);
            ap[jb>>1][(jb&1)*2 + 0] = reinterpret_cast<unsigned&>(e0);
            ap[jb>>1][(jb&1)*2 + 1] = reinterpret_cast<unsigned&>(e1);
        }

        // ---- O += P @ V ; L += P @ 1  (V via ldmatrix.trans) ----
        #pragma unroll
        for (int c = 0; c < 4; c++){
            #pragma unroll
            for (int jp = 0; jp < 4; jp++){
                unsigned bv[4];
                ldm4t(bv, vAddrT + kb + c*2304 + jp*32);
                mma16(accO[2*jp  ], ap[c], &bv[0]);
                mma16(accO[2*jp+1], ap[c], &bv[2]);
            }
            mma16(accL, ap[c], onesv);
        }

        mb_arrive(mbE + buf*8);          // this thread done reading tile kt
    }

    const float inv0 = 1.0f / accL[0], inv1 = 1.0f / accL[2];
    const int r0 = q0 + warp*16 + g, r1 = r0 + 8;
    #pragma unroll
    for (int jb = 0; jb < 8; jb++){
        int c = jb*8 + 2*tig;
        *(__half2*)&Og[r0*HD + c] = __floats2half2_rn(accO[jb][0]*inv0, accO[jb][1]*inv0);
        *(__half2*)&Og[r1*HD + c] = __floats2half2_rn(accO[jb][2]*inv1, accO[jb][3]*inv1);
    }
}

// ---------------- fused 7x7x2 conv + sigmoid + gate multiply ----------------
// One block per token: 98 threads compute conv terms in parallel, 192 scale.
__global__ __launch_bounds__(192) void convgate_k(const float* __restrict__ sa_w,
                                                  float* __restrict__ out)
{
    const int tok = blockIdx.x;          // b*NTOK + n
    __shared__ float sacc;
    __shared__ float sg;
    const int tid = threadIdx.x;
    if (tid == 0) sacc = 0.f;
    __syncthreads();
    if (tid < 98){
        int ch = tid / 49, k = tid % 49, ki = k / 7, kj = k % 7;
        int b = tok >= NTOK; int n = tok - b*NTOK;
        int hh = n / HWID, ww = n % HWID;
        int y = hh + ki - 3, x = ww + kj - 3;
        if ((unsigned)y < (unsigned)HWID && (unsigned)x < (unsigned)HWID){
            int base = b*NTOK + y*HWID + x;
            float v;
            if (ch == 0) v = g_psum[base] * (1.0f / CDIM);
            else {
                int kk = g_pmaxi[base];
                v = __int_as_float((kk >= 0) ? kk : (kk ^ 0x7FFFFFFF));
            }
            atomicAdd(&sacc, sa_w[ch*49 + k] * v);
        }
    }
    __syncthreads();
    if (tid == 0) sg = 1.0f / (1.0f + __expf(-sacc));
    __syncthreads();
    const float gg = sg;
    float4 v = ((const float4*)(g_P + (size_t)tok*CDIM))[tid];
    v.x *= gg; v.y *= gg; v.z *= gg; v.w *= gg;
    ((float4*)out)[(size_t)tok*(CDIM/4) + tid] = v;
}

// ---------------- launch ----------------
extern "C" void kernel_launch(void* const* d_in, const int* in_sizes, int n_in,
                              void* d_out, int out_size)
{
    (void)in_sizes; (void)n_in; (void)out_size;
    const float* q_in   = (const float*)d_in[0];
    const float* kv_in  = (const float*)d_in[1];
    const float* q_w    = (const float*)d_in[2];
    const float* q_b    = (const float*)d_in[3];
    const float* kv_w   = (const float*)d_in[4];
    const float* kv_b   = (const float*)d_in[5];
    const float* proj_w = (const float*)d_in[6];
    const float* proj_b = (const float*)d_in[7];
    const float* sa_w   = (const float*)d_in[8];

    const int gemm_smem = 3 * 24576;            // 73728
    const int attn_smem = 27648 + NBUF*18432;   // 138240
    cudaFuncSetAttribute(gemm_h2<0>, cudaFuncAttributeMaxDynamicSharedMemorySize, gemm_smem);
    cudaFuncSetAttribute(gemm_h2<2>, cudaFuncAttributeMaxDynamicSharedMemorySize, gemm_smem);
    cudaFuncSetAttribute(attn_h3,    cudaFuncAttributeMaxDynamicSharedMemorySize, attn_smem);

    cvt_all<<<9216, 256>>>(q_in, kv_in, q_w, kv_w, proj_w);

    gemm_h2<0><<<dim3(18, 72), 128, gemm_smem>>>(q_b, kv_b);     // fused Q + KV proj

    attn_h3<<<dim3(12, 24), 384, attn_smem>>>();

    gemm_h2<2><<<dim3( 6, 72), 128, gemm_smem>>>(proj_b, nullptr);

    convgate_k<<<BATCH*NTOK, 192>>>(sa_w, (float*)d_out);
}